// round 13
// baseline (speedup 1.0000x reference)
#include <cuda_runtime.h>
#include <cuda_bf16.h>
#include <cuda_fp16.h>
#include <cstdint>
#include <math.h>

#define BB 256
#define NN 128
#define EE 2048
#define DD 512
#define RR 1024
#define OO 10
#define LL 5

// ---------------- scratch ----------------------------------------------------
__device__ float  g_hA[(size_t)BB * NN * DD];
__device__ float  g_hB[(size_t)BB * NN * DD];
__device__ __half g_hHi[(size_t)BB * NN * DD];   // fp16-split of current cp_pool input
__device__ __half g_hLo[(size_t)BB * NN * DD];
__device__ __half g_WtHi[(size_t)LL * RR * DD];  // W^T split, K-major (L, R, D)
__device__ __half g_WtLo[(size_t)LL * RR * DD];
__device__ float  g_bias[LL * RR];
__device__ float  g_pooled[(size_t)LL * BB * RR];
__device__ int    g_rowptr[BB * (NN + 1)];
__device__ int    g_col[BB * EE];

// ---------------- helpers ----------------------------------------------------
__device__ __forceinline__ uint32_t smem_u32(const void* p) {
    uint32_t a;
    asm("{ .reg .u64 t; cvta.to.shared.u64 t, %1; cvt.u32.u64 %0, t; }" : "=r"(a) : "l"(p));
    return a;
}
// fast tanh: e = exp(2x) (clamped), t = (e-1)/(e+1); ~1e-6 rel accuracy.
__device__ __forceinline__ float ftanh(float x) {
    float xc = fminf(fmaxf(x, -15.0f), 15.0f);
    float e = __expf(2.0f * xc);
    return (e - 1.0f) * __frcp_rn(e + 1.0f);
}
// split float4 -> hi/lo fp16 quads, store packed (8B each)
__device__ __forceinline__ void split_store4(__half* Hi, __half* Lo, size_t idx4, float4 v) {
    __half hx = __float2half_rn(v.x), hy = __float2half_rn(v.y);
    __half hz = __float2half_rn(v.z), hw = __float2half_rn(v.w);
    __half lx = __float2half_rn(v.x - __half2float(hx));
    __half ly = __float2half_rn(v.y - __half2float(hy));
    __half lz = __float2half_rn(v.z - __half2float(hz));
    __half lw = __float2half_rn(v.w - __half2float(hw));
    __half2 h01 = __halves2half2(hx, hy), h23 = __halves2half2(hz, hw);
    __half2 l01 = __halves2half2(lx, ly), l23 = __halves2half2(lz, lw);
    uint2 hv, lv;
    hv.x = *(uint32_t*)&h01; hv.y = *(uint32_t*)&h23;
    lv.x = *(uint32_t*)&l01; lv.y = *(uint32_t*)&l23;
    ((uint2*)Hi)[idx4] = hv;
    ((uint2*)Lo)[idx4] = lv;
}
__device__ __forceinline__ void ldsm_x4(uint32_t* f, uint32_t addr) {
    asm volatile("ldmatrix.sync.aligned.m8n8.x4.shared.b16 {%0,%1,%2,%3}, [%4];"
                 : "=r"(f[0]), "=r"(f[1]), "=r"(f[2]), "=r"(f[3]) : "r"(addr));
}
__device__ __forceinline__ void mma_f16(float* c, const uint32_t* a, const uint32_t* b) {
    asm volatile(
        "mma.sync.aligned.m16n8k16.row.col.f32.f16.f16.f32 "
        "{%0,%1,%2,%3}, {%4,%5,%6,%7}, {%8,%9}, {%0,%1,%2,%3};"
        : "+f"(c[0]), "+f"(c[1]), "+f"(c[2]), "+f"(c[3])
        : "r"(a[0]), "r"(a[1]), "r"(a[2]), "r"(a[3]), "r"(b[0]), "r"(b[1]));
}
__device__ __forceinline__ void cpa16(uint32_t dst, const __half* src) {
    asm volatile("cp.async.cg.shared.global [%0], [%1], 16;" :: "r"(dst), "l"(src));
}
#define CP_COMMIT() asm volatile("cp.async.commit_group;" ::: "memory")
#define CP_WAIT(n)  asm volatile("cp.async.wait_group %0;" :: "n"(n) : "memory")

// ---------------- W transpose + split + bias ---------------------------------
__global__ void transpose_W_kernel(const float* __restrict__ W) {
    __shared__ float tile[32][33];
    int l = blockIdx.z;
    int k0 = blockIdx.x * 32, r0 = blockIdx.y * 32;
    int tx = threadIdx.x, ty = threadIdx.y;  // (32, 8)
    const float* Wl = W + (size_t)l * 513 * RR;
#pragma unroll
    for (int i = 0; i < 32; i += 8)
        tile[ty + i][tx] = Wl[(size_t)(k0 + ty + i) * RR + r0 + tx];
    __syncthreads();
#pragma unroll
    for (int i = 0; i < 32; i += 8) {
        float v = tile[tx][ty + i];
        __half hi = __float2half_rn(v);
        size_t idx = (size_t)l * RR * DD + (size_t)(r0 + ty + i) * DD + k0 + tx;
        g_WtHi[idx] = hi;
        g_WtLo[idx] = __float2half_rn(v - __half2float(hi));
    }
}
__global__ void bias_kernel(const float* __restrict__ W) {
    int i = blockIdx.x * 256 + threadIdx.x;
    if (i < LL * RR) {
        int l = i / RR, r = i % RR;
        g_bias[i] = W[(size_t)l * 513 * RR + (size_t)DD * RR + r];
    }
}

// ---------------- split x (layer 0 input) ------------------------------------
__global__ void split_x_kernel(const float* __restrict__ x) {
    size_t i = (size_t)blockIdx.x * 256 + threadIdx.x;  // float4 index
    float4 v = ((const float4*)x)[i];
    split_store4(g_hHi, g_hLo, i, v);
}

// ---------------- CSR build --------------------------------------------------
__global__ void csr_build_kernel(const int* __restrict__ edges) {
    int b = blockIdx.x;
    __shared__ int cnt[NN];
    __shared__ int off[NN + 1];
    int t = threadIdx.x;
    cnt[t] = 0;
    __syncthreads();
    const int* src = edges + (size_t)b * 2 * EE;
    const int* dst = src + EE;
    for (int e = t; e < EE; e += NN) atomicAdd(&cnt[dst[e]], 1);
    __syncthreads();
    if (t == 0) {
        int s = 0;
        for (int n = 0; n < NN; n++) { off[n] = s; s += cnt[n]; }
        off[NN] = s;
    }
    __syncthreads();
    g_rowptr[b * (NN + 1) + t] = off[t];
    if (t == 0) g_rowptr[b * (NN + 1) + NN] = off[NN];
    cnt[t] = off[t];
    __syncthreads();
    for (int e = t; e < EE; e += NN) {
        int d = dst[e];
        int pos = atomicAdd(&cnt[d], 1);
        g_col[b * EE + pos] = src[e];
    }
}

// ---------------- aggregate (+ fp16 split of output), MLP-unrolled -----------
__global__ void aggregate_kernel(const float* __restrict__ h,
                                 float* __restrict__ hnext) {
    int n = blockIdx.x;
    int b = blockIdx.y;
    int t = threadIdx.x;
    const float4* hb = (const float4*)(h + (size_t)b * NN * DD);
    float4 acc = hb[n * (DD / 4) + t];
    int beg = g_rowptr[b * (NN + 1) + n];
    int end = g_rowptr[b * (NN + 1) + n + 1];
    const int* col = g_col + b * EE;
    int i = beg;
    for (; i + 4 <= end; i += 4) {
        int s0 = col[i], s1 = col[i + 1], s2 = col[i + 2], s3 = col[i + 3];
        float4 v0 = hb[s0 * (DD / 4) + t];
        float4 v1 = hb[s1 * (DD / 4) + t];
        float4 v2 = hb[s2 * (DD / 4) + t];
        float4 v3 = hb[s3 * (DD / 4) + t];
        acc.x += v0.x; acc.y += v0.y; acc.z += v0.z; acc.w += v0.w;
        acc.x += v1.x; acc.y += v1.y; acc.z += v1.z; acc.w += v1.w;
        acc.x += v2.x; acc.y += v2.y; acc.z += v2.z; acc.w += v2.w;
        acc.x += v3.x; acc.y += v3.y; acc.z += v3.z; acc.w += v3.w;
    }
    for (; i < end; i++) {
        int s = col[i];
        float4 v = hb[s * (DD / 4) + t];
        acc.x += v.x; acc.y += v.y; acc.z += v.z; acc.w += v.w;
    }
    size_t idx = (size_t)b * NN * (DD / 4) + n * (DD / 4) + t;
    ((float4*)hnext)[idx] = acc;
    split_store4(g_hHi, g_hLo, idx, acc);
}

// ---------------- fp16x3 mma.sync cp_pool (512 threads, 256x256 tile) ---------
// CTA: 2 batches, 256 r-rows (M) x 256 node-cols (N), K=512 in 32-wide chunks
// (16 chunks). 16 warps 4(M) x 4(N); warp tile 64M x 64N.
// Rows pack hi|lo: 128B row = [hi k0..31 | lo k0..31] fp16. Swizzle unit^=(row&7).
// Stage: A 256 rows (32KB) + B 256 rows (32KB) = 64KB; 3 stages, 2-deep prefetch.
// acc += Alo*Bhi + Ahi*Blo + Ahi*Bhi per k16 step (order as R11).
#define SA 0
#define SB 32768
#define STAGE 65536
#define NSTG 3
#define NCH 16
#define SMEM_MMA (NSTG * STAGE + 2 * 256 * 2 * 4)

__global__ __launch_bounds__(512, 1) void cp_pool_mma_kernel(
    const __half* __restrict__ hHi,   // (B, N, D)
    const __half* __restrict__ hLo,
    const __half* __restrict__ WtHi,  // (R, D) this layer
    const __half* __restrict__ WtLo,
    const float* __restrict__ bias,   // (R)
    float* __restrict__ pooled) {     // (B, R) this layer
    extern __shared__ char smem[];
    float (*red)[256][2] = (float (*)[256][2])(smem + NSTG * STAGE);
    uint32_t sb = smem_u32(smem);

    const int tid = threadIdx.x;
    const int lane = tid & 31, wid = tid >> 5;
    const int wm = wid >> 2, wn = wid & 3;       // 4 x 4 warp grid
    const int g = lane >> 2, tig = lane & 3;
    const int r0 = blockIdx.x * 256;
    const int b0 = blockIdx.y * 2;

    const __half* Ahi = WtHi + (size_t)r0 * DD;
    const __half* Alo = WtLo + (size_t)r0 * DD;
    const __half* Bhi = hHi + (size_t)b0 * NN * DD;   // 256 rows x 512
    const __half* Blo = hLo + (size_t)b0 * NN * DD;

    // copy mapping (16B units = 8 fp16). A: 256 rows x 8 units = 2048 slots,
    // 4/thread; u<4 -> hi (k sub u*8), u>=4 -> lo ((u-4)*8). Same for B.
    uint32_t adst[4]; const __half* aptr[4];
    uint32_t bdst[4]; const __half* bptr[4];
#pragma unroll
    for (int i = 0; i < 4; i++) {
        int slot = tid + 512 * i;
        int row = slot >> 3, u = slot & 7;
        uint32_t d = row * 128 + ((u ^ (row & 7)) << 4);
        adst[i] = SA + d;
        bdst[i] = SB + d;
        size_t off = (size_t)row * DD + (u & 3) * 8;
        aptr[i] = (u < 4 ? Ahi : Alo) + off;
        bptr[i] = (u < 4 ? Bhi : Blo) + off;
    }

    // ldmatrix lane addressing (fp16 m16n8k16 fragments)
    const int lane7 = lane & 7;
    const int khalfA = lane >> 4;          // A: k-half (+8 k)
    const int arow8  = (lane >> 3) & 1;    // A: +8 m rows
    const int bkh    = (lane >> 3) & 1;    // B: k-half
    const int brow8  = (lane >> 4) & 1;    // B: +8 n rows
    uint32_t aoff[4], boff[4];
#pragma unroll
    for (int mt = 0; mt < 4; mt++)
        aoff[mt] = SA + (wm * 64 + mt * 16 + arow8 * 8 + lane7) * 128;
#pragma unroll
    for (int p = 0; p < 4; p++)
        boff[p] = SB + (wn * 64 + p * 16 + brow8 * 8 + lane7) * 128;

    float acc[4][8][4];
#pragma unroll
    for (int mt = 0; mt < 4; mt++)
#pragma unroll
        for (int nt = 0; nt < 8; nt++)
#pragma unroll
            for (int e = 0; e < 4; e++) acc[mt][nt][e] = 0.0f;

    auto issue = [&](int kc, int s) {
        uint32_t su = sb + s * STAGE;
        int k0 = kc * 32;
#pragma unroll
        for (int i = 0; i < 4; i++) {
            cpa16(adst[i] + su - sb + sb, aptr[i] + k0);  // su + adst[i] rel
        }
#pragma unroll
        for (int i = 0; i < 4; i++) {
            cpa16(su + bdst[i], bptr[i] + k0);
        }
        CP_COMMIT();
    };
    // note: rewrite A loop cleanly (avoid the odd expression above)
    auto issueA = [&](int kc, int s) {
        uint32_t su = sb + s * STAGE;
        int k0 = kc * 32;
#pragma unroll
        for (int i = 0; i < 4; i++) cpa16(su + adst[i], aptr[i] + k0);
#pragma unroll
        for (int i = 0; i < 4; i++) cpa16(su + bdst[i], bptr[i] + k0);
        CP_COMMIT();
    };

    issueA(0, 0);
    issueA(1, 1);
    issueA(2, 2);

    for (int kc = 0; kc < NCH; kc++) {
        int s = kc % NSTG;
        if (kc < NCH - 2)       CP_WAIT(2);
        else if (kc == NCH - 2) CP_WAIT(1);
        else                    CP_WAIT(0);
        __syncthreads();
        uint32_t su = sb + s * STAGE;
#pragma unroll
        for (int st = 0; st < 2; st++) {           // 2 k16 steps per 32-chunk
            uint32_t uah = (((st * 2 + khalfA)) ^ lane7) << 4;
            uint32_t ual = (((st * 2 + khalfA) + 4) ^ lane7) << 4;
            uint32_t ubh = (((st * 2 + bkh)) ^ lane7) << 4;
            uint32_t ubl = (((st * 2 + bkh) + 4) ^ lane7) << 4;
            uint32_t bh[4][4], bl4[4][4];
#pragma unroll
            for (int p = 0; p < 4; p++) {
                ldsm_x4(bh[p], su + boff[p] + ubh);
                ldsm_x4(bl4[p], su + boff[p] + ubl);
            }
#pragma unroll
            for (int mt = 0; mt < 4; mt++) {
                uint32_t ah[4], al[4];
                ldsm_x4(ah, su + aoff[mt] + uah);
                ldsm_x4(al, su + aoff[mt] + ual);
#pragma unroll
                for (int nt = 0; nt < 8; nt++) {
                    int p = nt >> 1, q = nt & 1;
                    uint32_t bhr[2] = { bh[p][q * 2], bh[p][q * 2 + 1] };
                    uint32_t blr[2] = { bl4[p][q * 2], bl4[p][q * 2 + 1] };
                    mma_f16(acc[mt][nt], al, bhr);   // Alo*Bhi
                    mma_f16(acc[mt][nt], ah, blr);   // Ahi*Blo
                    mma_f16(acc[mt][nt], ah, bhr);   // Ahi*Bhi
                }
            }
        }
        __syncthreads();
        if (kc + NSTG < NCH) issueA(kc + NSTG, s);
    }

    // epilogue: tanh(z + bias), product over this warp's 64 node columns
#pragma unroll
    for (int mt = 0; mt < 4; mt++) {
        int rl = wm * 64 + mt * 16 + g;
        float blo = bias[r0 + rl];
        float bhi = bias[r0 + rl + 8];
        float plo = 1.0f, phi = 1.0f;
#pragma unroll
        for (int nt = 0; nt < 8; nt++) {
            plo *= ftanh(acc[mt][nt][0] + blo) * ftanh(acc[mt][nt][1] + blo);
            phi *= ftanh(acc[mt][nt][2] + bhi) * ftanh(acc[mt][nt][3] + bhi);
        }
        plo *= __shfl_xor_sync(0xffffffffu, plo, 1);
        plo *= __shfl_xor_sync(0xffffffffu, plo, 2);
        phi *= __shfl_xor_sync(0xffffffffu, phi, 1);
        phi *= __shfl_xor_sync(0xffffffffu, phi, 2);
        if (tig == 0) {
            red[wn >> 1][rl][wn & 1] = plo;
            red[wn >> 1][rl + 8][wn & 1] = phi;
        }
    }
    __syncthreads();
    {
        int bl = tid >> 8, rl = tid & 255;   // 512 threads: 2 batches x 256 r
        float v = red[bl][rl][0] * red[bl][rl][1];
        pooled[(size_t)(b0 + bl) * RR + r0 + rl] = v;
    }
}

// ---------------- score (all layers fused, one launch) ------------------------
__global__ void score_all_kernel(const float* __restrict__ pooledL,  // (L,B,R)
                                 const float* __restrict__ lin_w,    // (L,R,O)
                                 const float* __restrict__ lin_b,    // (L,O)
                                 float* __restrict__ out) {
    int b = blockIdx.x;
    int t = threadIdx.x;
    float acc[OO];
#pragma unroll
    for (int o = 0; o < OO; o++) acc[o] = 0.0f;
    for (int l = 0; l < LL; l++) {
        const float* pb = pooledL + ((size_t)l * BB + b) * RR;
        const float* wl = lin_w + (size_t)l * RR * OO;
        for (int r = t; r < RR; r += 256) {
            float pv = pb[r];
            const float* wr = wl + (size_t)r * OO;
#pragma unroll
            for (int o = 0; o < OO; o++) acc[o] += pv * wr[o];
        }
    }
    __shared__ float s[256][OO];
#pragma unroll
    for (int o = 0; o < OO; o++) s[t][o] = acc[o];
    __syncthreads();
    if (t < OO) {
        float v = 0.0f;
        for (int l = 0; l < LL; l++) v += lin_b[l * OO + t];
        for (int i = 0; i < 256; i++) v += s[i][t];
        out[b * OO + t] = v;
    }
}

// ---------------- launch -----------------------------------------------------
extern "C" void kernel_launch(void* const* d_in, const int* in_sizes, int n_in,
                              void* d_out, int out_size) {
    const float* x     = (const float*)d_in[0];
    const int*   edges = (const int*)  d_in[1];
    const float* W_cp  = (const float*)d_in[2];
    const float* lin_w = (const float*)d_in[3];
    const float* lin_b = (const float*)d_in[4];
    float* out = (float*)d_out;

    float *hA, *hB, *pooled, *bias;
    __half *hHi, *hLo, *WtHi, *WtLo;
    cudaGetSymbolAddress((void**)&hA, g_hA);
    cudaGetSymbolAddress((void**)&hB, g_hB);
    cudaGetSymbolAddress((void**)&hHi, g_hHi);
    cudaGetSymbolAddress((void**)&hLo, g_hLo);
    cudaGetSymbolAddress((void**)&pooled, g_pooled);
    cudaGetSymbolAddress((void**)&WtHi, g_WtHi);
    cudaGetSymbolAddress((void**)&WtLo, g_WtLo);
    cudaGetSymbolAddress((void**)&bias, g_bias);

    static bool attr_set = false;
    if (!attr_set) {
        cudaFuncSetAttribute(cp_pool_mma_kernel,
                             cudaFuncAttributeMaxDynamicSharedMemorySize, SMEM_MMA);
        attr_set = true;
    }

    transpose_W_kernel<<<dim3(DD / 32, RR / 32, LL), dim3(32, 8)>>>(W_cp);
    bias_kernel<<<(LL * RR + 255) / 256, 256>>>(W_cp);
    csr_build_kernel<<<BB, NN>>>(edges);
    split_x_kernel<<<(int)(((size_t)BB * NN * DD / 4) / 256), 256>>>(x);

    // layer 0
    cp_pool_mma_kernel<<<dim3(RR / 256, BB / 2), 512, SMEM_MMA>>>(
        hHi, hLo, WtHi, WtLo, bias, pooled);

    const float* hcur = x;
    float* bufs[2] = {hA, hB};
    for (int l = 1; l < LL; l++) {
        float* hnext = bufs[(l - 1) & 1];
        aggregate_kernel<<<dim3(NN, BB), 128>>>(hcur, hnext);
        cp_pool_mma_kernel<<<dim3(RR / 256, BB / 2), 512, SMEM_MMA>>>(
            hHi, hLo,
            WtHi + (size_t)l * RR * DD, WtLo + (size_t)l * RR * DD,
            bias + (size_t)l * RR, pooled + (size_t)l * BB * RR);
        hcur = hnext;
    }
    score_all_kernel<<<BB, 256>>>(pooled, lin_w, lin_b, out);
}

// round 14
// speedup vs baseline: 3.2264x; 3.2264x over previous
#include <cuda_runtime.h>
#include <cuda_bf16.h>
#include <cuda_fp16.h>
#include <cstdint>
#include <math.h>

#define BB 256
#define NN 128
#define EE 2048
#define DD 512
#define RR 1024
#define OO 10
#define LL 5
#define HSZ ((size_t)BB * NN * DD)

// ---------------- scratch ----------------------------------------------------
__device__ float  g_hA[HSZ];
__device__ float  g_hB[HSZ];
__device__ __half g_hHiL[LL * HSZ];   // per-layer fp16 split (hi)
__device__ __half g_hLoL[LL * HSZ];   // per-layer fp16 split (lo)
__device__ __half g_WtHi[(size_t)LL * RR * DD];
__device__ __half g_WtLo[(size_t)LL * RR * DD];
__device__ float  g_bias[LL * RR];
__device__ float  g_pooled[(size_t)LL * BB * RR];
__device__ int    g_rowptr[BB * (NN + 1)];
__device__ int    g_col[BB * EE];

// ---------------- helpers ----------------------------------------------------
__device__ __forceinline__ uint32_t smem_u32(const void* p) {
    uint32_t a;
    asm("{ .reg .u64 t; cvta.to.shared.u64 t, %1; cvt.u32.u64 %0, t; }" : "=r"(a) : "l"(p));
    return a;
}
__device__ __forceinline__ float ftanh(float x) {
    float xc = fminf(fmaxf(x, -15.0f), 15.0f);
    float e = __expf(2.0f * xc);
    return (e - 1.0f) * __frcp_rn(e + 1.0f);
}
__device__ __forceinline__ void split_store4(__half* Hi, __half* Lo, size_t idx4, float4 v) {
    __half hx = __float2half_rn(v.x), hy = __float2half_rn(v.y);
    __half hz = __float2half_rn(v.z), hw = __float2half_rn(v.w);
    __half lx = __float2half_rn(v.x - __half2float(hx));
    __half ly = __float2half_rn(v.y - __half2float(hy));
    __half lz = __float2half_rn(v.z - __half2float(hz));
    __half lw = __float2half_rn(v.w - __half2float(hw));
    __half2 h01 = __halves2half2(hx, hy), h23 = __halves2half2(hz, hw);
    __half2 l01 = __halves2half2(lx, ly), l23 = __halves2half2(lz, lw);
    uint2 hv, lv;
    hv.x = *(uint32_t*)&h01; hv.y = *(uint32_t*)&h23;
    lv.x = *(uint32_t*)&l01; lv.y = *(uint32_t*)&l23;
    ((uint2*)Hi)[idx4] = hv;
    ((uint2*)Lo)[idx4] = lv;
}
__device__ __forceinline__ void ldsm_x4(uint32_t* f, uint32_t addr) {
    asm volatile("ldmatrix.sync.aligned.m8n8.x4.shared.b16 {%0,%1,%2,%3}, [%4];"
                 : "=r"(f[0]), "=r"(f[1]), "=r"(f[2]), "=r"(f[3]) : "r"(addr));
}
__device__ __forceinline__ void mma_f16(float* c, const uint32_t* a, const uint32_t* b) {
    asm volatile(
        "mma.sync.aligned.m16n8k16.row.col.f32.f16.f16.f32 "
        "{%0,%1,%2,%3}, {%4,%5,%6,%7}, {%8,%9}, {%0,%1,%2,%3};"
        : "+f"(c[0]), "+f"(c[1]), "+f"(c[2]), "+f"(c[3])
        : "r"(a[0]), "r"(a[1]), "r"(a[2]), "r"(a[3]), "r"(b[0]), "r"(b[1]));
}
__device__ __forceinline__ void cpa16(uint32_t dst, const __half* src) {
    asm volatile("cp.async.cg.shared.global [%0], [%1], 16;" :: "r"(dst), "l"(src));
}
#define CP_COMMIT() asm volatile("cp.async.commit_group;" ::: "memory")
#define CP_WAIT(n)  asm volatile("cp.async.wait_group %0;" :: "n"(n) : "memory")

// ---------------- W transpose + split + bias ---------------------------------
__global__ void transpose_W_kernel(const float* __restrict__ W) {
    __shared__ float tile[32][33];
    int l = blockIdx.z;
    int k0 = blockIdx.x * 32, r0 = blockIdx.y * 32;
    int tx = threadIdx.x, ty = threadIdx.y;  // (32, 8)
    const float* Wl = W + (size_t)l * 513 * RR;
#pragma unroll
    for (int i = 0; i < 32; i += 8)
        tile[ty + i][tx] = Wl[(size_t)(k0 + ty + i) * RR + r0 + tx];
    __syncthreads();
#pragma unroll
    for (int i = 0; i < 32; i += 8) {
        float v = tile[tx][ty + i];
        __half hi = __float2half_rn(v);
        size_t idx = (size_t)l * RR * DD + (size_t)(r0 + ty + i) * DD + k0 + tx;
        g_WtHi[idx] = hi;
        g_WtLo[idx] = __float2half_rn(v - __half2float(hi));
    }
}
__global__ void bias_kernel(const float* __restrict__ W) {
    int i = blockIdx.x * 256 + threadIdx.x;
    if (i < LL * RR) {
        int l = i / RR, r = i % RR;
        g_bias[i] = W[(size_t)l * 513 * RR + (size_t)DD * RR + r];
    }
}

// ---------------- split x (layer 0 input) ------------------------------------
__global__ void split_x_kernel(const float* __restrict__ x,
                               __half* __restrict__ Hi, __half* __restrict__ Lo) {
    size_t i = (size_t)blockIdx.x * 256 + threadIdx.x;  // float4 index
    float4 v = ((const float4*)x)[i];
    split_store4(Hi, Lo, i, v);
}

// ---------------- CSR build --------------------------------------------------
__global__ void csr_build_kernel(const int* __restrict__ edges) {
    int b = blockIdx.x;
    __shared__ int cnt[NN];
    __shared__ int off[NN + 1];
    int t = threadIdx.x;
    cnt[t] = 0;
    __syncthreads();
    const int* src = edges + (size_t)b * 2 * EE;
    const int* dst = src + EE;
    for (int e = t; e < EE; e += NN) atomicAdd(&cnt[dst[e]], 1);
    __syncthreads();
    if (t == 0) {
        int s = 0;
        for (int n = 0; n < NN; n++) { off[n] = s; s += cnt[n]; }
        off[NN] = s;
    }
    __syncthreads();
    g_rowptr[b * (NN + 1) + t] = off[t];
    if (t == 0) g_rowptr[b * (NN + 1) + NN] = off[NN];
    cnt[t] = off[t];
    __syncthreads();
    for (int e = t; e < EE; e += NN) {
        int d = dst[e];
        int pos = atomicAdd(&cnt[d], 1);
        g_col[b * EE + pos] = src[e];
    }
}

// ---------------- aggregate (+ fp16 split to per-layer buffer) ----------------
__global__ void aggregate_kernel(const float* __restrict__ h,
                                 float* __restrict__ hnext,
                                 __half* __restrict__ Hi,
                                 __half* __restrict__ Lo) {
    int n = blockIdx.x;
    int b = blockIdx.y;
    int t = threadIdx.x;
    const float4* hb = (const float4*)(h + (size_t)b * NN * DD);
    float4 acc = hb[n * (DD / 4) + t];
    int beg = g_rowptr[b * (NN + 1) + n];
    int end = g_rowptr[b * (NN + 1) + n + 1];
    const int* col = g_col + b * EE;
    int i = beg;
    for (; i + 4 <= end; i += 4) {
        int s0 = col[i], s1 = col[i + 1], s2 = col[i + 2], s3 = col[i + 3];
        float4 v0 = hb[s0 * (DD / 4) + t];
        float4 v1 = hb[s1 * (DD / 4) + t];
        float4 v2 = hb[s2 * (DD / 4) + t];
        float4 v3 = hb[s3 * (DD / 4) + t];
        acc.x += v0.x; acc.y += v0.y; acc.z += v0.z; acc.w += v0.w;
        acc.x += v1.x; acc.y += v1.y; acc.z += v1.z; acc.w += v1.w;
        acc.x += v2.x; acc.y += v2.y; acc.z += v2.z; acc.w += v2.w;
        acc.x += v3.x; acc.y += v3.y; acc.z += v3.z; acc.w += v3.w;
    }
    for (; i < end; i++) {
        int s = col[i];
        float4 v = hb[s * (DD / 4) + t];
        acc.x += v.x; acc.y += v.y; acc.z += v.z; acc.w += v.w;
    }
    size_t idx = (size_t)b * NN * (DD / 4) + n * (DD / 4) + t;
    ((float4*)hnext)[idx] = acc;
    split_store4(Hi, Lo, idx, acc);
}

// ---------------- fp16x3 mma.sync cp_pool (R11 structure, verbatim) -----------
// CTA: 2 batches, 128 r-rows (M) x 256 node-cols (N), K=512 in 64-wide chunks
// (8 chunks). 8 warps 2(M) x 4(N); warp tile 64M x 64N.
// acc += Ahi*Bhi + Alo*Bhi + Ahi*Blo via mma.m16n8k16.f16, fp32 accumulate.
#define AHI 0
#define ALO 16384
#define BHI 32768
#define BLO 65536
#define STAGE 98304
#define SMEM_MMA (2 * STAGE + 2 * 128 * 2 * 4)

__global__ __launch_bounds__(256, 1) void cp_pool_mma_kernel(
    const __half* __restrict__ hHi,   // (B, N, D)
    const __half* __restrict__ hLo,
    const __half* __restrict__ WtHi,  // (R, D) this layer
    const __half* __restrict__ WtLo,
    const float* __restrict__ bias,   // (R)
    float* __restrict__ pooled) {     // (B, R) this layer
    extern __shared__ char smem[];
    float (*red)[128][2] = (float (*)[128][2])(smem + 2 * STAGE);
    uint32_t sb = smem_u32(smem);

    const int tid = threadIdx.x;
    const int lane = tid & 31, wid = tid >> 5;
    const int wm = wid >> 2, wn = wid & 3;
    const int g = lane >> 2, tig = lane & 3;
    const int r0 = blockIdx.x * 128;
    const int b0 = blockIdx.y * 2;

    const __half* Ahi = WtHi + (size_t)r0 * DD;
    const __half* Alo = WtLo + (size_t)r0 * DD;
    const __half* Bhi = hHi + (size_t)b0 * NN * DD;   // 256 rows x 512
    const __half* Blo = hLo + (size_t)b0 * NN * DD;

    uint32_t adst[4]; size_t asrc[4];
#pragma unroll
    for (int i = 0; i < 4; i++) {
        int slot = tid + 256 * i;
        int row = slot >> 3, u = slot & 7;
        adst[i] = row * 128 + ((u ^ (row & 7)) << 4);
        asrc[i] = (size_t)row * DD + u * 8;
    }
    uint32_t bdst[8]; size_t bsrc[8];
#pragma unroll
    for (int i = 0; i < 8; i++) {
        int slot = tid + 256 * i;
        int row = slot >> 3, u = slot & 7;
        bdst[i] = row * 128 + ((u ^ (row & 7)) << 4);
        bsrc[i] = (size_t)row * DD + u * 8;
    }

    const int lane7 = lane & 7;
    const int khalfA = lane >> 4;          // A: k-half (+8 k)
    const int arow8  = (lane >> 3) & 1;    // A: +8 m rows
    const int bkh    = (lane >> 3) & 1;    // B: k-half
    const int brow8  = (lane >> 4) & 1;    // B: +8 n rows
    uint32_t aoff[4], boff[4];
#pragma unroll
    for (int mt = 0; mt < 4; mt++)
        aoff[mt] = (wm * 64 + mt * 16 + arow8 * 8 + lane7) * 128;
#pragma unroll
    for (int p = 0; p < 4; p++)
        boff[p] = (wn * 64 + p * 16 + brow8 * 8 + lane7) * 128;

    float acc[4][8][4];
#pragma unroll
    for (int mt = 0; mt < 4; mt++)
#pragma unroll
        for (int nt = 0; nt < 8; nt++)
#pragma unroll
            for (int e = 0; e < 4; e++) acc[mt][nt][e] = 0.0f;

    auto issue = [&](int kc, int s) {
        uint32_t su = sb + s * STAGE;
        int k0 = kc * 64;
#pragma unroll
        for (int i = 0; i < 4; i++) {
            cpa16(su + AHI + adst[i], Ahi + asrc[i] + k0);
            cpa16(su + ALO + adst[i], Alo + asrc[i] + k0);
        }
#pragma unroll
        for (int i = 0; i < 8; i++) {
            cpa16(su + BHI + bdst[i], Bhi + bsrc[i] + k0);
            cpa16(su + BLO + bdst[i], Blo + bsrc[i] + k0);
        }
        CP_COMMIT();
    };

    issue(0, 0);
    issue(1, 1);

    for (int kc = 0; kc < 8; kc++) {
        int s = kc & 1;
        if (kc < 7) CP_WAIT(1); else CP_WAIT(0);
        __syncthreads();
        uint32_t su = sb + s * STAGE;
#pragma unroll
        for (int st = 0; st < 4; st++) {           // 4 k16 steps per 64-chunk
            uint32_t ua = (((st * 2 + khalfA) ^ lane7) << 4);
            uint32_t ub = (((st * 2 + bkh) ^ lane7) << 4);
            uint32_t bh[4][4], bl4[4][4];
#pragma unroll
            for (int p = 0; p < 4; p++) {
                ldsm_x4(bh[p], su + BHI + boff[p] + ub);
                ldsm_x4(bl4[p], su + BLO + boff[p] + ub);
            }
#pragma unroll
            for (int mt = 0; mt < 4; mt++) {
                uint32_t ah[4], al[4];
                ldsm_x4(ah, su + AHI + aoff[mt] + ua);
                ldsm_x4(al, su + ALO + aoff[mt] + ua);
#pragma unroll
                for (int nt = 0; nt < 8; nt++) {
                    int p = nt >> 1, q = nt & 1;
                    uint32_t bhr[2] = { bh[p][q * 2], bh[p][q * 2 + 1] };
                    uint32_t blr[2] = { bl4[p][q * 2], bl4[p][q * 2 + 1] };
                    mma_f16(acc[mt][nt], al, bhr);   // Alo*Bhi
                    mma_f16(acc[mt][nt], ah, blr);   // Ahi*Blo
                    mma_f16(acc[mt][nt], ah, bhr);   // Ahi*Bhi
                }
            }
        }
        __syncthreads();
        if (kc + 2 < 8) issue(kc + 2, s);
    }

    // epilogue: tanh(z + bias), product over this warp's 64 node columns
#pragma unroll
    for (int mt = 0; mt < 4; mt++) {
        int rl = wm * 64 + mt * 16 + g;
        float blo = bias[r0 + rl];
        float bhi = bias[r0 + rl + 8];
        float plo = 1.0f, phi = 1.0f;
#pragma unroll
        for (int nt = 0; nt < 8; nt++) {
            plo *= ftanh(acc[mt][nt][0] + blo) * ftanh(acc[mt][nt][1] + blo);
            phi *= ftanh(acc[mt][nt][2] + bhi) * ftanh(acc[mt][nt][3] + bhi);
        }
        plo *= __shfl_xor_sync(0xffffffffu, plo, 1);
        plo *= __shfl_xor_sync(0xffffffffu, plo, 2);
        phi *= __shfl_xor_sync(0xffffffffu, phi, 1);
        phi *= __shfl_xor_sync(0xffffffffu, phi, 2);
        if (tig == 0) {
            red[wn >> 1][rl][wn & 1] = plo;
            red[wn >> 1][rl + 8][wn & 1] = phi;
        }
    }
    __syncthreads();
    {
        int bl = tid >> 7, rl = tid & 127;
        float v = red[bl][rl][0] * red[bl][rl][1];
        pooled[(size_t)(b0 + bl) * RR + r0 + rl] = v;
    }
}

// ---------------- score (all layers fused, one launch) ------------------------
__global__ void score_all_kernel(const float* __restrict__ pooledL,  // (L,B,R)
                                 const float* __restrict__ lin_w,    // (L,R,O)
                                 const float* __restrict__ lin_b,    // (L,O)
                                 float* __restrict__ out) {
    int b = blockIdx.x;
    int t = threadIdx.x;
    float acc[OO];
#pragma unroll
    for (int o = 0; o < OO; o++) acc[o] = 0.0f;
    for (int l = 0; l < LL; l++) {
        const float* pb = pooledL + ((size_t)l * BB + b) * RR;
        const float* wl = lin_w + (size_t)l * RR * OO;
        for (int r = t; r < RR; r += 256) {
            float pv = pb[r];
            const float* wr = wl + (size_t)r * OO;
#pragma unroll
            for (int o = 0; o < OO; o++) acc[o] += pv * wr[o];
        }
    }
    __shared__ float s[256][OO];
#pragma unroll
    for (int o = 0; o < OO; o++) s[t][o] = acc[o];
    __syncthreads();
    if (t < OO) {
        float v = 0.0f;
        for (int l = 0; l < LL; l++) v += lin_b[l * OO + t];
        for (int i = 0; i < 256; i++) v += s[i][t];
        out[b * OO + t] = v;
    }
}

// ---------------- launch (fork/join: aggregates overlap cp_pool) --------------
extern "C" void kernel_launch(void* const* d_in, const int* in_sizes, int n_in,
                              void* d_out, int out_size) {
    const float* x     = (const float*)d_in[0];
    const int*   edges = (const int*)  d_in[1];
    const float* W_cp  = (const float*)d_in[2];
    const float* lin_w = (const float*)d_in[3];
    const float* lin_b = (const float*)d_in[4];
    float* out = (float*)d_out;

    float *hA, *hB, *pooled, *bias;
    __half *hHiL, *hLoL, *WtHi, *WtLo;
    cudaGetSymbolAddress((void**)&hA, g_hA);
    cudaGetSymbolAddress((void**)&hB, g_hB);
    cudaGetSymbolAddress((void**)&hHiL, g_hHiL);
    cudaGetSymbolAddress((void**)&hLoL, g_hLoL);
    cudaGetSymbolAddress((void**)&pooled, g_pooled);
    cudaGetSymbolAddress((void**)&WtHi, g_WtHi);
    cudaGetSymbolAddress((void**)&WtLo, g_WtLo);
    cudaGetSymbolAddress((void**)&bias, g_bias);

    static cudaStream_t s2 = nullptr;
    static cudaEvent_t evStart = nullptr;
    static cudaEvent_t evA[LL];
    if (!s2) {
        cudaStreamCreateWithFlags(&s2, cudaStreamNonBlocking);
        cudaEventCreateWithFlags(&evStart, cudaEventDisableTiming);
        for (int l = 0; l < LL; l++)
            cudaEventCreateWithFlags(&evA[l], cudaEventDisableTiming);
        cudaFuncSetAttribute(cp_pool_mma_kernel,
                             cudaFuncAttributeMaxDynamicSharedMemorySize, SMEM_MMA);
    }

    // fork side stream off the (capturing) default stream
    cudaEventRecord(evStart, 0);
    cudaStreamWaitEvent(s2, evStart, 0);

    // side stream: csr, split x -> buf0, aggregate chain -> buf l
    csr_build_kernel<<<BB, NN, 0, s2>>>(edges);
    split_x_kernel<<<(int)((HSZ / 4) / 256), 256, 0, s2>>>(x, hHiL, hLoL);
    cudaEventRecord(evA[0], s2);
    {
        const float* hcur = x;
        float* bufs[2] = {hA, hB};
        for (int l = 1; l < LL; l++) {
            float* hnext = bufs[(l - 1) & 1];
            aggregate_kernel<<<dim3(NN, BB), 128, 0, s2>>>(
                hcur, hnext, hHiL + (size_t)l * HSZ, hLoL + (size_t)l * HSZ);
            cudaEventRecord(evA[l], s2);
            hcur = hnext;
        }
    }

    // main stream: W prep, then per-layer cp_pool gated on aggregate events
    transpose_W_kernel<<<dim3(DD / 32, RR / 32, LL), dim3(32, 8)>>>(W_cp);
    bias_kernel<<<(LL * RR + 255) / 256, 256>>>(W_cp);

    for (int l = 0; l < LL; l++) {
        cudaStreamWaitEvent(0, evA[l], 0);   // joins s2 work into capture
        cp_pool_mma_kernel<<<dim3(RR / 128, BB / 2), 256, SMEM_MMA>>>(
            hHiL + (size_t)l * HSZ, hLoL + (size_t)l * HSZ,
            WtHi + (size_t)l * RR * DD, WtLo + (size_t)l * RR * DD,
            bias + (size_t)l * RR, pooled + (size_t)l * BB * RR);
    }
    score_all_kernel<<<BB, 256>>>(pooled, lin_w, lin_b, out);
}